// round 13
// baseline (speedup 1.0000x reference)
#include <cuda_runtime.h>
#include <cuda_bf16.h>
#include <cstdint>

#define THREADS 512
#define TILE_E  64
#define KTOT    896
#define HTOT    384
#define NCH     14
#define NWARP_N 8
#define NB_PER_W 6
#define E_MAX   200704

// ---------- packed weights ----------
#define BPK_TOTAL (2 * 49152 + 12 * 81920)
__device__ __align__(16) unsigned char g_Bpk[BPK_TOTAL];
__device__ float g_b1[HTOT];
__device__ float g_w2[HTOT];

// ---------- edge compaction ----------
__device__ int g_valid[E_MAX];
__device__ int g_invalid[E_MAX];
__device__ int g_cnt[2];

__global__ void zero_kernel() { g_cnt[0] = 0; g_cnt[1] = 0; }

__global__ void compact_kernel(const int* __restrict__ edge,
                               const int* __restrict__ mask, int E)
{
    int e = blockIdx.x * blockDim.x + threadIdx.x;
    if (e < E) {
        int s = edge[2 * e], d = edge[2 * e + 1];
        if (mask[s] && mask[d]) { int p = atomicAdd(&g_cnt[0], 1); g_valid[p] = e; }
        else                    { int p = atomicAdd(&g_cnt[1], 1); g_invalid[p] = e; }
    }
}

__global__ void pack_kernel(
    const float* __restrict__ sw1, const float* __restrict__ sb1, const float* __restrict__ sw2,
    const float* __restrict__ cw1, const float* __restrict__ cb1, const float* __restrict__ cw2,
    const float* __restrict__ mw1, const float* __restrict__ mb1, const float* __restrict__ mw2)
{
    int idx = blockIdx.x * blockDim.x + threadIdx.x;
    if (idx < KTOT * HTOT) {
        int k = idx / HTOT;
        int j = idx - k * HTOT;
        float v = 0.f;
        if (j < 64) {
            if (k < 128) v = sw1[k * 64 + j];
        } else if (j < 256) {
            if (k >= 128) v = cw1[(k - 128) * 192 + (j - 64)];
        } else {
            v = mw1[k * 128 + (j - 256)];
        }
        int c  = k >> 6;
        int nb = j >> 3;
        int abi = -1;
        if (c < 2) {
            if (nb < 8)        abi = nb;
            else if (nb >= 32) abi = 8 + (nb - 32);
        } else {
            if (nb >= 32)      abi = 24 + (nb - 32);
            else if (nb >= 8)  abi = nb - 8;
        }
        if (abi >= 0) {
            __nv_bfloat16 vh = __float2bfloat16(v);
            __nv_bfloat16 vl = __float2bfloat16(v - __bfloat162float(vh));
            int kk = k & 63;
            int ks = kk >> 4;
            int kr = kk & 15;
            int nr = j & 7;
            int lane = nr * 4 + ((kr & 7) >> 1);
            int reg  = kr >> 3;
            int pair = kr & 1;
            uint32_t cbase = (c < 2) ? (uint32_t)c * 49152u
                                     : 98304u + (uint32_t)(c - 2) * 81920u;
            uint32_t slot16 = cbase + (((uint32_t)abi * 4 + ks) * 32 + lane) * 16;
            uint32_t sub = 2 * (reg * 2 + pair);
            *(__nv_bfloat16*)(g_Bpk + slot16 + sub)     = vh;
            *(__nv_bfloat16*)(g_Bpk + slot16 + 8 + sub) = vl;
        }
    } else if (idx < KTOT * HTOT + HTOT) {
        int j = idx - KTOT * HTOT;
        float b, w;
        if (j < 64)       { b = sb1[j];       w = sw2[j]; }
        else if (j < 256) { b = cb1[j - 64];  w = cw2[j - 64]; }
        else              { b = mb1[j - 256]; w = mw2[j - 256]; }
        g_b1[j] = b;
        g_w2[j] = w;
    }
}

__device__ __forceinline__ void mma16816(float* d, const uint32_t* a, const uint32_t b0, const uint32_t b1) {
    asm volatile(
        "mma.sync.aligned.m16n8k16.row.col.f32.bf16.bf16.f32 "
        "{%0,%1,%2,%3}, {%4,%5,%6,%7}, {%8,%9}, {%0,%1,%2,%3};"
        : "+f"(d[0]), "+f"(d[1]), "+f"(d[2]), "+f"(d[3])
        : "r"(a[0]), "r"(a[1]), "r"(a[2]), "r"(a[3]), "r"(b0), "r"(b1));
}

__device__ __forceinline__ uint32_t pack_bf16x2(float x, float y) {
    __nv_bfloat162 h = __floats2bfloat162_rn(x, y);
    return *reinterpret_cast<uint32_t*>(&h);
}

__device__ __forceinline__ void cp_async16(uint32_t saddr, const void* gptr) {
    asm volatile("cp.async.cg.shared.global [%0], [%1], 16;" :: "r"(saddr), "l"(gptr));
}
#define CP_COMMIT() asm volatile("cp.async.commit_group;" ::: "memory")
#define CP_WAIT0()  asm volatile("cp.async.wait_group 0;" ::: "memory")

#define ABLK 528
#define AREG (16 * ABLK)
#define BBUF 81920

#define A_OFF    0
#define B_OFF    (4 * AREG)
#define RED_OFF  (B_OFF + 2 * BBUF)
#define SRC_OFF  (RED_OFF + 6144)
#define DST_OFF  (SRC_OFF + 256)
#define GE_OFF   (DST_OFF + 256)
#define SM_TOTAL (GE_OFF + 256)

template <int NACT>
__device__ __forceinline__ void mma_chunk(
    float acc[2][NB_PER_W][4],
    const char* ah, const char* al, const char* bB,
    int mw, int lane, const int* slist, const int* alist)
{
    #pragma unroll
    for (int ks = 0; ks < 4; ks++) {
        uint32_t afh[2][4], afl[2][4];
        #pragma unroll
        for (int f = 0; f < 2; f++) {
            uint32_t boff = (uint32_t)((mw * 2 + f) * 4 + ks) * ABLK + lane * 16;
            uint4 vh = *(const uint4*)(ah + boff);
            uint4 vl = *(const uint4*)(al + boff);
            afh[f][0] = vh.x; afh[f][1] = vh.y; afh[f][2] = vh.z; afh[f][3] = vh.w;
            afl[f][0] = vl.x; afl[f][1] = vl.y; afl[f][2] = vl.z; afl[f][3] = vl.w;
        }
        #pragma unroll
        for (int i = 0; i < NACT; i++) {
            const int sl = slist[i];
            uint4 v = *(const uint4*)(bB + (((uint32_t)alist[i] * 4 + ks) * 32 + lane) * 16);
            #pragma unroll
            for (int f = 0; f < 2; f++) {
                mma16816(acc[f][sl], afh[f], v.x, v.y);
                mma16816(acc[f][sl], afh[f], v.z, v.w);
                mma16816(acc[f][sl], afl[f], v.x, v.y);
            }
        }
    }
}

// One tile of work. FULL: all paths + softmax combine. STRUCT: structural only.
template <bool FULL>
__device__ void tile_body(
    int ebase, int nv, const int* __restrict__ elist,
    char* smem, uint32_t smem_u32,
    const float* __restrict__ z, const float* __restrict__ chem,
    const int*   __restrict__ edge,
    const float* __restrict__ sb2, const float* __restrict__ cb2,
    const float* __restrict__ mb2, const float* __restrict__ pw,
    float* __restrict__ out)
{
    const int tid  = threadIdx.x;
    const int wid  = tid >> 5;
    const int lane = tid & 31;
    const int nw   = wid & 7;
    const int mw   = wid >> 3;

    const int  NCHE  = FULL ? NCH : 2;
    const uint32_t B0SZ = FULL ? 49152u : 16384u;

    int*   Ssrc = (int*)(smem + SRC_OFF);
    int*   Sdst = (int*)(smem + DST_OFF);
    int*   Sge  = (int*)(smem + GE_OFF);
    float* red  = (float*)(smem + RED_OFF);

    if (tid < TILE_E) {
        int li = ebase + tid;
        int ge = elist[(li < nv) ? li : (nv - 1)];
        Sge[tid] = (li < nv) ? ge : -1;
        Ssrc[tid] = edge[2 * ge + 0];
        Sdst[tid] = edge[2 * ge + 1];
    }
    for (int i = tid; i < NWARP_N * 3 * TILE_E; i += THREADS)
        red[i] = 0.f;
    __syncthreads();

    const int ge_ = tid >> 3;
    const int q   = tid & 7;
    const int r   = ge_ & 15;
    const int fm  = ge_ >> 4;
    const uint32_t abase = (uint32_t)(fm * 4 + (q >> 1)) * ABLK
                         + (uint32_t)((r & 7) * 64 + (r >> 3) * 4 + (q & 1) * 8);
    const int srow = Ssrc[ge_];
    const int drow = Sdst[ge_];

    const int sl_z[3] = { 0, 4, 5 };
    const int ab_z[3] = { nw, 8 + 2 * nw, 9 + 2 * nw };
    const int sl_c[5] = { 1, 2, 3, 4, 5 };
    const int ab_c[5] = { 3 * nw, 3 * nw + 1, 3 * nw + 2, 24 + 2 * nw, 25 + 2 * nw };
    const int sl_s[1] = { 0 };
    const int ab_s[1] = { nw };

    float4 ga[2], gb[2];
    {
        const float* sp = z + (size_t)srow * 128 + q * 8;
        const float* dp = z + (size_t)drow * 128 + q * 8;
        ga[0] = *(const float4*)(sp);     ga[1] = *(const float4*)(sp + 4);
        gb[0] = *(const float4*)(dp);     gb[1] = *(const float4*)(dp + 4);
    }
    {
        for (uint32_t i = tid; i < B0SZ / 16; i += THREADS)
            cp_async16(smem_u32 + B_OFF + i * 16, g_Bpk + i * 16);
        CP_COMMIT();
    }

    float acc[2][NB_PER_W][4];
    #pragma unroll
    for (int a = 0; a < 2; a++)
        #pragma unroll
        for (int b = 0; b < NB_PER_W; b++)
            #pragma unroll
            for (int qq = 0; qq < 4; qq++) acc[a][b][qq] = 0.f;

    #pragma unroll 1
    for (int c = 0; c < NCHE; c++) {
        // ---- stage A(c) ----
        {
            char* sah = smem + A_OFF + ((c & 1) * 2 + 0) * AREG;
            char* sal = smem + A_OFF + ((c & 1) * 2 + 1) * AREG;
            #pragma unroll
            for (int i = 0; i < 2; i++) {
                float p0 = ga[i].x * gb[i].x;
                float p1 = ga[i].y * gb[i].y;
                float p2 = ga[i].z * gb[i].z;
                float p3 = ga[i].w * gb[i].w;
                __nv_bfloat16 h0 = __float2bfloat16(p0), h1 = __float2bfloat16(p1);
                __nv_bfloat16 h2 = __float2bfloat16(p2), h3 = __float2bfloat16(p3);
                float l0 = p0 - __bfloat162float(h0);
                float l1 = p1 - __bfloat162float(h1);
                float l2 = p2 - __bfloat162float(h2);
                float l3 = p3 - __bfloat162float(h3);
                uint32_t hi01 = ((uint32_t)__bfloat16_as_ushort(h0)) | ((uint32_t)__bfloat16_as_ushort(h1) << 16);
                uint32_t hi23 = ((uint32_t)__bfloat16_as_ushort(h2)) | ((uint32_t)__bfloat16_as_ushort(h3) << 16);
                uint32_t lo01 = pack_bf16x2(l0, l1);
                uint32_t lo23 = pack_bf16x2(l2, l3);
                uint32_t a0 = abase + (uint32_t)(i * 32);
                uint32_t a1 = a0 + 16;
                *(uint32_t*)(sah + a0) = hi01;
                *(uint32_t*)(sah + a1) = hi23;
                *(uint32_t*)(sal + a0) = lo01;
                *(uint32_t*)(sal + a1) = lo23;
            }
        }
        CP_WAIT0();
        __syncthreads();

        // ---- cp.async B(c+1) ----
        if (c + 1 < NCHE) {
            int cn = c + 1;
            uint32_t nb16, cbase;
            if (FULL) {
                nb16  = ((cn < 2) ? 49152u : 81920u) >> 4;
                cbase = (cn < 2) ? (uint32_t)cn * 49152u
                                 : 98304u + (uint32_t)(cn - 2) * 81920u;
            } else {
                nb16  = 16384u >> 4;
                cbase = (uint32_t)cn * 49152u;
            }
            uint32_t bdst = smem_u32 + B_OFF + (uint32_t)(cn & 1) * BBUF;
            const unsigned char* gsrc = g_Bpk + cbase;
            for (uint32_t i = tid; i < nb16; i += THREADS)
                cp_async16(bdst + i * 16, gsrc + i * 16);
            CP_COMMIT();
        }

        // ---- prefetch gather A(c+1) ----
        if (c + 1 < NCHE) {
            int cn = c + 1;
            const float* basep = (cn < 2) ? z : chem;
            int ldr = (cn < 2) ? 128 : 768;
            int kb  = (cn < 2) ? cn * 64 : (cn - 2) * 64;
            const float* sp = basep + (size_t)srow * ldr + kb + q * 8;
            const float* dp = basep + (size_t)drow * ldr + kb + q * 8;
            ga[0] = *(const float4*)(sp);     ga[1] = *(const float4*)(sp + 4);
            gb[0] = *(const float4*)(dp);     gb[1] = *(const float4*)(dp + 4);
        }

        // ---- MMA ----
        {
            const char* ah = smem + A_OFF + ((c & 1) * 2 + 0) * AREG;
            const char* al = smem + A_OFF + ((c & 1) * 2 + 1) * AREG;
            const char* bB = smem + B_OFF + (c & 1) * BBUF;
            if (FULL) {
                if (c < 2) mma_chunk<3>(acc, ah, al, bB, mw, lane, sl_z, ab_z);
                else       mma_chunk<5>(acc, ah, al, bB, mw, lane, sl_c, ab_c);
            } else {
                mma_chunk<1>(acc, ah, al, bB, mw, lane, sl_s, ab_s);
            }
        }
    }
    __syncthreads();

    // ---- epilogue ----
    {
        const int nbg[NB_PER_W] = { nw, 8 + nw * 3, 9 + nw * 3, 10 + nw * 3,
                                    32 + nw * 2, 33 + nw * 2 };
        const int qc = (lane & 3) * 2;
        float ps[4][3];
        #pragma unroll
        for (int s = 0; s < 4; s++)
            #pragma unroll
            for (int p = 0; p < 3; p++) ps[s][p] = 0.f;

        const int NSL = FULL ? NB_PER_W : 1;
        #pragma unroll
        for (int sl = 0; sl < NSL; sl++) {
            int col0 = nbg[sl] * 8;
            int p = (sl == 0) ? 0 : (sl < 4) ? 1 : 2;
            float bb0 = g_b1[col0 + qc],     bb1 = g_b1[col0 + qc + 1];
            float ww0 = g_w2[col0 + qc],     ww1 = g_w2[col0 + qc + 1];
            #pragma unroll
            for (int f = 0; f < 2; f++) {
                const float* a = acc[f][sl];
                ps[f * 2 + 0][p] += fmaxf(a[0] + bb0, 0.f) * ww0 + fmaxf(a[1] + bb1, 0.f) * ww1;
                ps[f * 2 + 1][p] += fmaxf(a[2] + bb0, 0.f) * ww0 + fmaxf(a[3] + bb1, 0.f) * ww1;
            }
        }
        #pragma unroll
        for (int s = 0; s < 4; s++)
            #pragma unroll
            for (int p = 0; p < 3; p++) {
                float v = ps[s][p];
                v += __shfl_xor_sync(0xffffffffu, v, 1);
                v += __shfl_xor_sync(0xffffffffu, v, 2);
                ps[s][p] = v;
            }
        if ((lane & 3) == 0) {
            #pragma unroll
            for (int f = 0; f < 2; f++)
                #pragma unroll
                for (int rr = 0; rr < 2; rr++) {
                    int el = (mw * 2 + f) * 16 + (lane >> 2) + rr * 8;
                    #pragma unroll
                    for (int p = 0; p < 3; p++)
                        red[(nw * 3 + p) * TILE_E + el] += ps[f * 2 + rr][p];
                }
        }
    }
    __syncthreads();

    if (tid < TILE_E && Sge[tid] >= 0) {
        float s0 = 0.f, s1 = 0.f, s2 = 0.f;
        #pragma unroll
        for (int w = 0; w < NWARP_N; w++) {
            s0 += red[(w * 3 + 0) * TILE_E + tid];
            s1 += red[(w * 3 + 1) * TILE_E + tid];
            s2 += red[(w * 3 + 2) * TILE_E + tid];
        }
        float res;
        if (FULL) {
            float p0 = pw[0], p1 = pw[1], p2 = pw[2];
            float mx = fmaxf(p0, fmaxf(p1, p2));
            float e0 = expf(p0 - mx), e1 = expf(p1 - mx), e2 = expf(p2 - mx);
            float inv = 1.f / (e0 + e1 + e2);
            float ss = s0 + sb2[0];
            float sc = s1 + cb2[0];
            float sm = s2 + mb2[0];
            res = (e0 * ss + e1 * sc + e2 * sm) * inv;
        } else {
            res = s0 + sb2[0];
        }
        out[Sge[tid]] = res;
    }
}

// Fused dispatcher: FULL tiles first (heavy), STRUCT tiles fill in as SMs free.
__global__ void __launch_bounds__(THREADS, 1)
decoder_all(
    const float* __restrict__ z, const float* __restrict__ chem,
    const int*   __restrict__ edge,
    const float* __restrict__ sb2, const float* __restrict__ cb2,
    const float* __restrict__ mb2, const float* __restrict__ pw,
    float* __restrict__ out)
{
    extern __shared__ __align__(16) char smem[];
    uint32_t smem_u32;
    asm("{ .reg .u64 t; cvta.to.shared.u64 t, %1; cvt.u32.u64 %0, t; }"
        : "=r"(smem_u32) : "l"(smem));

    const int nv  = g_cnt[0];
    const int ni  = g_cnt[1];
    const int nvt = (nv + TILE_E - 1) / TILE_E;
    const int bid = blockIdx.x;

    if (bid < nvt) {
        tile_body<true>(bid * TILE_E, nv, g_valid, smem, smem_u32,
                        z, chem, edge, sb2, cb2, mb2, pw, out);
    } else {
        int t = bid - nvt;
        if (t * TILE_E < ni)
            tile_body<false>(t * TILE_E, ni, g_invalid, smem, smem_u32,
                             z, chem, edge, sb2, cb2, mb2, pw, out);
    }
}

extern "C" void kernel_launch(void* const* d_in, const int* in_sizes, int n_in,
                              void* d_out, int out_size)
{
    const float* z    = (const float*)d_in[0];
    const float* chem = (const float*)d_in[1];
    const int*   edge = (const int*)d_in[2];
    const int*   mask = (const int*)d_in[3];
    const float* sw1  = (const float*)d_in[4];
    const float* sb1  = (const float*)d_in[5];
    const float* sw2  = (const float*)d_in[6];
    const float* sb2  = (const float*)d_in[7];
    const float* cw1  = (const float*)d_in[8];
    const float* cb1  = (const float*)d_in[9];
    const float* cw2  = (const float*)d_in[10];
    const float* cb2  = (const float*)d_in[11];
    const float* mw1  = (const float*)d_in[12];
    const float* mb1  = (const float*)d_in[13];
    const float* mw2  = (const float*)d_in[14];
    const float* mb2  = (const float*)d_in[15];
    const float* pw   = (const float*)d_in[16];
    float*       out  = (float*)d_out;

    const int E = in_sizes[2] / 2;

    zero_kernel<<<1, 1>>>();
    compact_kernel<<<(E + 511) / 512, 512>>>(edge, mask, E);
    {
        int total = KTOT * HTOT + HTOT;
        pack_kernel<<<(total + 255) / 256, 256>>>(sw1, sb1, sw2,
                                                  cw1, cb1, cw2,
                                                  mw1, mb1, mw2);
    }

    cudaFuncSetAttribute(decoder_all,
                         cudaFuncAttributeMaxDynamicSharedMemorySize, SM_TOTAL);

    // Tile counts: nvt + nit <= ceil(E/64) + 1  (split rounding adds at most 1)
    const int nblocks = (E + TILE_E - 1) / TILE_E + 1;
    decoder_all<<<nblocks, THREADS, SM_TOTAL>>>(
        z, chem, edge, sb2, cb2, mb2, pw, out);
}

// round 15
// speedup vs baseline: 1.2977x; 1.2977x over previous
#include <cuda_runtime.h>
#include <cuda_bf16.h>
#include <cstdint>

#define THREADS 512
#define TILE_E  64
#define KTOT    896
#define HTOT    384
#define NCH     14
#define NWARP_N 8
#define NB_PER_W 6
#define E_MAX   200704
#define NT_STRUCT 4            // tiles per CTA in the struct kernel

// ---------- packed weights ----------
#define BPK_TOTAL (2 * 49152 + 12 * 81920)
__device__ __align__(16) unsigned char g_Bpk[BPK_TOTAL];
__device__ float g_b1[HTOT];
__device__ float g_w2[HTOT];

// ---------- edge compaction ----------
__device__ int g_valid[E_MAX];
__device__ int g_invalid[E_MAX];
__device__ int g_cnt[2];

__global__ void zero_kernel() { g_cnt[0] = 0; g_cnt[1] = 0; }

__global__ void compact_kernel(const int* __restrict__ edge,
                               const int* __restrict__ mask, int E)
{
    int e = blockIdx.x * blockDim.x + threadIdx.x;
    if (e < E) {
        int s = edge[2 * e], d = edge[2 * e + 1];
        if (mask[s] && mask[d]) { int p = atomicAdd(&g_cnt[0], 1); g_valid[p] = e; }
        else                    { int p = atomicAdd(&g_cnt[1], 1); g_invalid[p] = e; }
    }
}

__global__ void pack_kernel(
    const float* __restrict__ sw1, const float* __restrict__ sb1, const float* __restrict__ sw2,
    const float* __restrict__ cw1, const float* __restrict__ cb1, const float* __restrict__ cw2,
    const float* __restrict__ mw1, const float* __restrict__ mb1, const float* __restrict__ mw2)
{
    int idx = blockIdx.x * blockDim.x + threadIdx.x;
    if (idx < KTOT * HTOT) {
        int k = idx / HTOT;
        int j = idx - k * HTOT;
        float v = 0.f;
        if (j < 64) {
            if (k < 128) v = sw1[k * 64 + j];
        } else if (j < 256) {
            if (k >= 128) v = cw1[(k - 128) * 192 + (j - 64)];
        } else {
            v = mw1[k * 128 + (j - 256)];
        }
        int c  = k >> 6;
        int nb = j >> 3;
        int abi = -1;
        if (c < 2) {
            if (nb < 8)        abi = nb;
            else if (nb >= 32) abi = 8 + (nb - 32);
        } else {
            if (nb >= 32)      abi = 24 + (nb - 32);
            else if (nb >= 8)  abi = nb - 8;
        }
        if (abi >= 0) {
            __nv_bfloat16 vh = __float2bfloat16(v);
            __nv_bfloat16 vl = __float2bfloat16(v - __bfloat162float(vh));
            int kk = k & 63;
            int ks = kk >> 4;
            int kr = kk & 15;
            int nr = j & 7;
            int lane = nr * 4 + ((kr & 7) >> 1);
            int reg  = kr >> 3;
            int pair = kr & 1;
            uint32_t cbase = (c < 2) ? (uint32_t)c * 49152u
                                     : 98304u + (uint32_t)(c - 2) * 81920u;
            uint32_t slot16 = cbase + (((uint32_t)abi * 4 + ks) * 32 + lane) * 16;
            uint32_t sub = 2 * (reg * 2 + pair);
            *(__nv_bfloat16*)(g_Bpk + slot16 + sub)     = vh;
            *(__nv_bfloat16*)(g_Bpk + slot16 + 8 + sub) = vl;
        }
    } else if (idx < KTOT * HTOT + HTOT) {
        int j = idx - KTOT * HTOT;
        float b, w;
        if (j < 64)       { b = sb1[j];       w = sw2[j]; }
        else if (j < 256) { b = cb1[j - 64];  w = cw2[j - 64]; }
        else              { b = mb1[j - 256]; w = mw2[j - 256]; }
        g_b1[j] = b;
        g_w2[j] = w;
    }
}

__device__ __forceinline__ void mma16816(float* d, const uint32_t* a, const uint32_t b0, const uint32_t b1) {
    asm volatile(
        "mma.sync.aligned.m16n8k16.row.col.f32.bf16.bf16.f32 "
        "{%0,%1,%2,%3}, {%4,%5,%6,%7}, {%8,%9}, {%0,%1,%2,%3};"
        : "+f"(d[0]), "+f"(d[1]), "+f"(d[2]), "+f"(d[3])
        : "r"(a[0]), "r"(a[1]), "r"(a[2]), "r"(a[3]), "r"(b0), "r"(b1));
}

__device__ __forceinline__ uint32_t pack_bf16x2(float x, float y) {
    __nv_bfloat162 h = __floats2bfloat162_rn(x, y);
    return *reinterpret_cast<uint32_t*>(&h);
}

__device__ __forceinline__ void cp_async16(uint32_t saddr, const void* gptr) {
    asm volatile("cp.async.cg.shared.global [%0], [%1], 16;" :: "r"(saddr), "l"(gptr));
}
#define CP_COMMIT() asm volatile("cp.async.commit_group;" ::: "memory")
#define CP_WAIT0()  asm volatile("cp.async.wait_group 0;" ::: "memory")

#define ABLK 528
#define AREG (16 * ABLK)
#define BBUF 81920

#define A_OFF    0
#define B_OFF    (4 * AREG)
#define RED_OFF  (B_OFF + 2 * BBUF)
#define SRC_OFF  (RED_OFF + 6144)
#define DST_OFF  (SRC_OFF + 256)
#define GE_OFF   (DST_OFF + 256)
#define SM_TOTAL (GE_OFF + 256)

template <int NACT>
__device__ __forceinline__ void mma_chunk(
    float acc[2][NB_PER_W][4],
    const char* ah, const char* al, const char* bB,
    int mw, int lane, const int* slist, const int* alist)
{
    #pragma unroll
    for (int ks = 0; ks < 4; ks++) {
        uint32_t afh[2][4], afl[2][4];
        #pragma unroll
        for (int f = 0; f < 2; f++) {
            uint32_t boff = (uint32_t)((mw * 2 + f) * 4 + ks) * ABLK + lane * 16;
            uint4 vh = *(const uint4*)(ah + boff);
            uint4 vl = *(const uint4*)(al + boff);
            afh[f][0] = vh.x; afh[f][1] = vh.y; afh[f][2] = vh.z; afh[f][3] = vh.w;
            afl[f][0] = vl.x; afl[f][1] = vl.y; afl[f][2] = vl.z; afl[f][3] = vl.w;
        }
        #pragma unroll
        for (int i = 0; i < NACT; i++) {
            const int sl = slist[i];
            uint4 v = *(const uint4*)(bB + (((uint32_t)alist[i] * 4 + ks) * 32 + lane) * 16);
            #pragma unroll
            for (int f = 0; f < 2; f++) {
                mma16816(acc[f][sl], afh[f], v.x, v.y);
                mma16816(acc[f][sl], afh[f], v.z, v.w);
                mma16816(acc[f][sl], afl[f], v.x, v.y);
            }
        }
    }
}

// One tile of work. FULL: all paths + softmax combine. STRUCT: structural only.
// __forceinline__ is load-bearing: an ABI call here spills (round-13 regression).
template <bool FULL>
__device__ __forceinline__ void tile_body(
    int ebase, int nv, const int* __restrict__ elist,
    char* smem, uint32_t smem_u32,
    const float* __restrict__ z, const float* __restrict__ chem,
    const int*   __restrict__ edge,
    const float* __restrict__ sb2, const float* __restrict__ cb2,
    const float* __restrict__ mb2, const float* __restrict__ pw,
    float* __restrict__ out)
{
    const int tid  = threadIdx.x;
    const int wid  = tid >> 5;
    const int lane = tid & 31;
    const int nw   = wid & 7;
    const int mw   = wid >> 3;

    const int  NCHE  = FULL ? NCH : 2;
    const uint32_t B0SZ = FULL ? 49152u : 16384u;

    int*   Ssrc = (int*)(smem + SRC_OFF);
    int*   Sdst = (int*)(smem + DST_OFF);
    int*   Sge  = (int*)(smem + GE_OFF);
    float* red  = (float*)(smem + RED_OFF);

    if (tid < TILE_E) {
        int li = ebase + tid;
        int ge = elist[(li < nv) ? li : (nv - 1)];
        Sge[tid] = (li < nv) ? ge : -1;
        Ssrc[tid] = edge[2 * ge + 0];
        Sdst[tid] = edge[2 * ge + 1];
    }
    for (int i = tid; i < NWARP_N * 3 * TILE_E; i += THREADS)
        red[i] = 0.f;
    __syncthreads();

    const int ge_ = tid >> 3;
    const int q   = tid & 7;
    const int r   = ge_ & 15;
    const int fm  = ge_ >> 4;
    const uint32_t abase = (uint32_t)(fm * 4 + (q >> 1)) * ABLK
                         + (uint32_t)((r & 7) * 64 + (r >> 3) * 4 + (q & 1) * 8);
    const int srow = Ssrc[ge_];
    const int drow = Sdst[ge_];

    const int sl_z[3] = { 0, 4, 5 };
    const int ab_z[3] = { nw, 8 + 2 * nw, 9 + 2 * nw };
    const int sl_c[5] = { 1, 2, 3, 4, 5 };
    const int ab_c[5] = { 3 * nw, 3 * nw + 1, 3 * nw + 2, 24 + 2 * nw, 25 + 2 * nw };
    const int sl_s[1] = { 0 };
    const int ab_s[1] = { nw };

    float4 ga[2], gb[2];
    {
        const float* sp = z + (size_t)srow * 128 + q * 8;
        const float* dp = z + (size_t)drow * 128 + q * 8;
        ga[0] = *(const float4*)(sp);     ga[1] = *(const float4*)(sp + 4);
        gb[0] = *(const float4*)(dp);     gb[1] = *(const float4*)(dp + 4);
    }
    {
        for (uint32_t i = tid; i < B0SZ / 16; i += THREADS)
            cp_async16(smem_u32 + B_OFF + i * 16, g_Bpk + i * 16);
        CP_COMMIT();
    }

    float acc[2][NB_PER_W][4];
    #pragma unroll
    for (int a = 0; a < 2; a++)
        #pragma unroll
        for (int b = 0; b < NB_PER_W; b++)
            #pragma unroll
            for (int qq = 0; qq < 4; qq++) acc[a][b][qq] = 0.f;

    #pragma unroll 1
    for (int c = 0; c < NCHE; c++) {
        // ---- stage A(c) ----
        {
            char* sah = smem + A_OFF + ((c & 1) * 2 + 0) * AREG;
            char* sal = smem + A_OFF + ((c & 1) * 2 + 1) * AREG;
            #pragma unroll
            for (int i = 0; i < 2; i++) {
                float p0 = ga[i].x * gb[i].x;
                float p1 = ga[i].y * gb[i].y;
                float p2 = ga[i].z * gb[i].z;
                float p3 = ga[i].w * gb[i].w;
                __nv_bfloat16 h0 = __float2bfloat16(p0), h1 = __float2bfloat16(p1);
                __nv_bfloat16 h2 = __float2bfloat16(p2), h3 = __float2bfloat16(p3);
                float l0 = p0 - __bfloat162float(h0);
                float l1 = p1 - __bfloat162float(h1);
                float l2 = p2 - __bfloat162float(h2);
                float l3 = p3 - __bfloat162float(h3);
                uint32_t hi01 = ((uint32_t)__bfloat16_as_ushort(h0)) | ((uint32_t)__bfloat16_as_ushort(h1) << 16);
                uint32_t hi23 = ((uint32_t)__bfloat16_as_ushort(h2)) | ((uint32_t)__bfloat16_as_ushort(h3) << 16);
                uint32_t lo01 = pack_bf16x2(l0, l1);
                uint32_t lo23 = pack_bf16x2(l2, l3);
                uint32_t a0 = abase + (uint32_t)(i * 32);
                uint32_t a1 = a0 + 16;
                *(uint32_t*)(sah + a0) = hi01;
                *(uint32_t*)(sah + a1) = hi23;
                *(uint32_t*)(sal + a0) = lo01;
                *(uint32_t*)(sal + a1) = lo23;
            }
        }
        CP_WAIT0();
        __syncthreads();

        // ---- cp.async B(c+1) ----
        if (c + 1 < NCHE) {
            int cn = c + 1;
            uint32_t nb16, cbase;
            if (FULL) {
                nb16  = ((cn < 2) ? 49152u : 81920u) >> 4;
                cbase = (cn < 2) ? (uint32_t)cn * 49152u
                                 : 98304u + (uint32_t)(cn - 2) * 81920u;
            } else {
                nb16  = 16384u >> 4;
                cbase = (uint32_t)cn * 49152u;
            }
            uint32_t bdst = smem_u32 + B_OFF + (uint32_t)(cn & 1) * BBUF;
            const unsigned char* gsrc = g_Bpk + cbase;
            for (uint32_t i = tid; i < nb16; i += THREADS)
                cp_async16(bdst + i * 16, gsrc + i * 16);
            CP_COMMIT();
        }

        // ---- prefetch gather A(c+1) ----
        if (c + 1 < NCHE) {
            int cn = c + 1;
            const float* basep = (cn < 2) ? z : chem;
            int ldr = (cn < 2) ? 128 : 768;
            int kb  = (cn < 2) ? cn * 64 : (cn - 2) * 64;
            const float* sp = basep + (size_t)srow * ldr + kb + q * 8;
            const float* dp = basep + (size_t)drow * ldr + kb + q * 8;
            ga[0] = *(const float4*)(sp);     ga[1] = *(const float4*)(sp + 4);
            gb[0] = *(const float4*)(dp);     gb[1] = *(const float4*)(dp + 4);
        }

        // ---- MMA ----
        {
            const char* ah = smem + A_OFF + ((c & 1) * 2 + 0) * AREG;
            const char* al = smem + A_OFF + ((c & 1) * 2 + 1) * AREG;
            const char* bB = smem + B_OFF + (c & 1) * BBUF;
            if (FULL) {
                if (c < 2) mma_chunk<3>(acc, ah, al, bB, mw, lane, sl_z, ab_z);
                else       mma_chunk<5>(acc, ah, al, bB, mw, lane, sl_c, ab_c);
            } else {
                mma_chunk<1>(acc, ah, al, bB, mw, lane, sl_s, ab_s);
            }
        }
    }
    __syncthreads();

    // ---- epilogue ----
    {
        const int nbg[NB_PER_W] = { nw, 8 + nw * 3, 9 + nw * 3, 10 + nw * 3,
                                    32 + nw * 2, 33 + nw * 2 };
        const int qc = (lane & 3) * 2;
        float ps[4][3];
        #pragma unroll
        for (int s = 0; s < 4; s++)
            #pragma unroll
            for (int p = 0; p < 3; p++) ps[s][p] = 0.f;

        const int NSL = FULL ? NB_PER_W : 1;
        #pragma unroll
        for (int sl = 0; sl < NSL; sl++) {
            int col0 = nbg[sl] * 8;
            int p = (sl == 0) ? 0 : (sl < 4) ? 1 : 2;
            float bb0 = g_b1[col0 + qc],     bb1 = g_b1[col0 + qc + 1];
            float ww0 = g_w2[col0 + qc],     ww1 = g_w2[col0 + qc + 1];
            #pragma unroll
            for (int f = 0; f < 2; f++) {
                const float* a = acc[f][sl];
                ps[f * 2 + 0][p] += fmaxf(a[0] + bb0, 0.f) * ww0 + fmaxf(a[1] + bb1, 0.f) * ww1;
                ps[f * 2 + 1][p] += fmaxf(a[2] + bb0, 0.f) * ww0 + fmaxf(a[3] + bb1, 0.f) * ww1;
            }
        }
        #pragma unroll
        for (int s = 0; s < 4; s++)
            #pragma unroll
            for (int p = 0; p < 3; p++) {
                float v = ps[s][p];
                v += __shfl_xor_sync(0xffffffffu, v, 1);
                v += __shfl_xor_sync(0xffffffffu, v, 2);
                ps[s][p] = v;
            }
        if ((lane & 3) == 0) {
            #pragma unroll
            for (int f = 0; f < 2; f++)
                #pragma unroll
                for (int rr = 0; rr < 2; rr++) {
                    int el = (mw * 2 + f) * 16 + (lane >> 2) + rr * 8;
                    #pragma unroll
                    for (int p = 0; p < 3; p++)
                        red[(nw * 3 + p) * TILE_E + el] += ps[f * 2 + rr][p];
                }
        }
    }
    __syncthreads();

    if (tid < TILE_E && Sge[tid] >= 0) {
        float s0 = 0.f, s1 = 0.f, s2 = 0.f;
        #pragma unroll
        for (int w = 0; w < NWARP_N; w++) {
            s0 += red[(w * 3 + 0) * TILE_E + tid];
            s1 += red[(w * 3 + 1) * TILE_E + tid];
            s2 += red[(w * 3 + 2) * TILE_E + tid];
        }
        float res;
        if (FULL) {
            float p0 = pw[0], p1 = pw[1], p2 = pw[2];
            float mx = fmaxf(p0, fmaxf(p1, p2));
            float e0 = expf(p0 - mx), e1 = expf(p1 - mx), e2 = expf(p2 - mx);
            float inv = 1.f / (e0 + e1 + e2);
            float ss = s0 + sb2[0];
            float sc = s1 + cb2[0];
            float sm = s2 + mb2[0];
            res = (e0 * ss + e1 * sc + e2 * sm) * inv;
        } else {
            res = s0 + sb2[0];
        }
        out[Sge[tid]] = res;
    }
    __syncthreads();   // protect smem reuse across loop iterations (struct kernel)
}

__global__ void __launch_bounds__(THREADS, 1)
decoder_full(
    const float* __restrict__ z, const float* __restrict__ chem,
    const int*   __restrict__ edge,
    const float* __restrict__ sb2, const float* __restrict__ cb2,
    const float* __restrict__ mb2, const float* __restrict__ pw,
    float* __restrict__ out)
{
    const int nv = g_cnt[0];
    const int ebase = blockIdx.x * TILE_E;
    if (ebase >= nv) return;
    extern __shared__ __align__(16) char smem[];
    uint32_t smem_u32;
    asm("{ .reg .u64 t; cvta.to.shared.u64 t, %1; cvt.u32.u64 %0, t; }"
        : "=r"(smem_u32) : "l"(smem));
    tile_body<true>(ebase, nv, g_valid, smem, smem_u32,
                    z, chem, edge, sb2, cb2, mb2, pw, out);
}

__global__ void __launch_bounds__(THREADS, 1)
decoder_struct(
    const float* __restrict__ z, const float* __restrict__ chem,
    const int*   __restrict__ edge,
    const float* __restrict__ sb2, const float* __restrict__ cb2,
    const float* __restrict__ mb2, const float* __restrict__ pw,
    float* __restrict__ out)
{
    const int ni = g_cnt[1];
    extern __shared__ __align__(16) char smem[];
    uint32_t smem_u32;
    asm("{ .reg .u64 t; cvta.to.shared.u64 t, %1; cvt.u32.u64 %0, t; }"
        : "=r"(smem_u32) : "l"(smem));
    #pragma unroll 1
    for (int t = 0; t < NT_STRUCT; t++) {
        int ebase = (blockIdx.x * NT_STRUCT + t) * TILE_E;
        if (ebase < ni)
            tile_body<false>(ebase, ni, g_invalid, smem, smem_u32,
                             z, chem, edge, sb2, cb2, mb2, pw, out);
    }
}

extern "C" void kernel_launch(void* const* d_in, const int* in_sizes, int n_in,
                              void* d_out, int out_size)
{
    const float* z    = (const float*)d_in[0];
    const float* chem = (const float*)d_in[1];
    const int*   edge = (const int*)d_in[2];
    const int*   mask = (const int*)d_in[3];
    const float* sw1  = (const float*)d_in[4];
    const float* sb1  = (const float*)d_in[5];
    const float* sw2  = (const float*)d_in[6];
    const float* sb2  = (const float*)d_in[7];
    const float* cw1  = (const float*)d_in[8];
    const float* cb1  = (const float*)d_in[9];
    const float* cw2  = (const float*)d_in[10];
    const float* cb2  = (const float*)d_in[11];
    const float* mw1  = (const float*)d_in[12];
    const float* mb1  = (const float*)d_in[13];
    const float* mw2  = (const float*)d_in[14];
    const float* mb2  = (const float*)d_in[15];
    const float* pw   = (const float*)d_in[16];
    float*       out  = (float*)d_out;

    const int E = in_sizes[2] / 2;

    zero_kernel<<<1, 1>>>();
    compact_kernel<<<(E + 511) / 512, 512>>>(edge, mask, E);
    {
        int total = KTOT * HTOT + HTOT;
        pack_kernel<<<(total + 255) / 256, 256>>>(sw1, sb1, sw2,
                                                  cw1, cb1, cw2,
                                                  mw1, mb1, mw2);
    }

    cudaFuncSetAttribute(decoder_full,
                         cudaFuncAttributeMaxDynamicSharedMemorySize, SM_TOTAL);
    cudaFuncSetAttribute(decoder_struct,
                         cudaFuncAttributeMaxDynamicSharedMemorySize, SM_TOTAL);

    const int ntiles = (E + TILE_E - 1) / TILE_E;
    decoder_full<<<ntiles, THREADS, SM_TOTAL>>>(
        z, chem, edge, sb2, cb2, mb2, pw, out);
    const int nsb = (ntiles + NT_STRUCT - 1) / NT_STRUCT;
    decoder_struct<<<nsb, THREADS, SM_TOTAL>>>(
        z, chem, edge, sb2, cb2, mb2, pw, out);
}

// round 16
// speedup vs baseline: 1.3882x; 1.0697x over previous
#include <cuda_runtime.h>
#include <cuda_bf16.h>
#include <cstdint>

#define THREADS 512
#define TILE_E  64
#define KTOT    896
#define HTOT    384
#define NCH     14
#define NWARP_N 8
#define NB_PER_W 6
#define E_MAX   200704

// ---------- packed weights ----------
#define BPK_TOTAL (2 * 49152 + 12 * 81920)
__device__ __align__(16) unsigned char g_Bpk[BPK_TOTAL];
__device__ float g_b1[HTOT];
__device__ float g_w2[HTOT];

// ---------- edge compaction ----------
__device__ int g_valid[E_MAX];
__device__ int g_invalid[E_MAX];
__device__ int g_cnt[2];

__global__ void zero_kernel() { g_cnt[0] = 0; g_cnt[1] = 0; }

__global__ void compact_kernel(const int* __restrict__ edge,
                               const int* __restrict__ mask, int E)
{
    int e = blockIdx.x * blockDim.x + threadIdx.x;
    if (e < E) {
        int s = edge[2 * e], d = edge[2 * e + 1];
        if (mask[s] && mask[d]) { int p = atomicAdd(&g_cnt[0], 1); g_valid[p] = e; }
        else                    { int p = atomicAdd(&g_cnt[1], 1); g_invalid[p] = e; }
    }
}

__global__ void pack_kernel(
    const float* __restrict__ sw1, const float* __restrict__ sb1, const float* __restrict__ sw2,
    const float* __restrict__ cw1, const float* __restrict__ cb1, const float* __restrict__ cw2,
    const float* __restrict__ mw1, const float* __restrict__ mb1, const float* __restrict__ mw2)
{
    int idx = blockIdx.x * blockDim.x + threadIdx.x;
    if (idx < KTOT * HTOT) {
        int k = idx / HTOT;
        int j = idx - k * HTOT;
        float v = 0.f;
        if (j < 64) {
            if (k < 128) v = sw1[k * 64 + j];
        } else if (j < 256) {
            if (k >= 128) v = cw1[(k - 128) * 192 + (j - 64)];
        } else {
            v = mw1[k * 128 + (j - 256)];
        }
        int c  = k >> 6;
        int nb = j >> 3;
        int abi = -1;
        if (c < 2) {
            if (nb < 8)        abi = nb;
            else if (nb >= 32) abi = 8 + (nb - 32);
        } else {
            if (nb >= 32)      abi = 24 + (nb - 32);
            else if (nb >= 8)  abi = nb - 8;
        }
        if (abi >= 0) {
            __nv_bfloat16 vh = __float2bfloat16(v);
            __nv_bfloat16 vl = __float2bfloat16(v - __bfloat162float(vh));
            int kk = k & 63;
            int ks = kk >> 4;
            int kr = kk & 15;
            int nr = j & 7;
            int lane = nr * 4 + ((kr & 7) >> 1);
            int reg  = kr >> 3;
            int pair = kr & 1;
            uint32_t cbase = (c < 2) ? (uint32_t)c * 49152u
                                     : 98304u + (uint32_t)(c - 2) * 81920u;
            uint32_t slot16 = cbase + (((uint32_t)abi * 4 + ks) * 32 + lane) * 16;
            uint32_t sub = 2 * (reg * 2 + pair);
            *(__nv_bfloat16*)(g_Bpk + slot16 + sub)     = vh;
            *(__nv_bfloat16*)(g_Bpk + slot16 + 8 + sub) = vl;
        }
    } else if (idx < KTOT * HTOT + HTOT) {
        int j = idx - KTOT * HTOT;
        float b, w;
        if (j < 64)       { b = sb1[j];       w = sw2[j]; }
        else if (j < 256) { b = cb1[j - 64];  w = cw2[j - 64]; }
        else              { b = mb1[j - 256]; w = mw2[j - 256]; }
        g_b1[j] = b;
        g_w2[j] = w;
    }
}

__device__ __forceinline__ void mma16816(float* d, const uint32_t* a, const uint32_t b0, const uint32_t b1) {
    asm volatile(
        "mma.sync.aligned.m16n8k16.row.col.f32.bf16.bf16.f32 "
        "{%0,%1,%2,%3}, {%4,%5,%6,%7}, {%8,%9}, {%0,%1,%2,%3};"
        : "+f"(d[0]), "+f"(d[1]), "+f"(d[2]), "+f"(d[3])
        : "r"(a[0]), "r"(a[1]), "r"(a[2]), "r"(a[3]), "r"(b0), "r"(b1));
}

__device__ __forceinline__ uint32_t pack_bf16x2(float x, float y) {
    __nv_bfloat162 h = __floats2bfloat162_rn(x, y);
    return *reinterpret_cast<uint32_t*>(&h);
}

__device__ __forceinline__ void cp_async16(uint32_t saddr, const void* gptr) {
    asm volatile("cp.async.cg.shared.global [%0], [%1], 16;" :: "r"(saddr), "l"(gptr));
}
#define CP_COMMIT() asm volatile("cp.async.commit_group;" ::: "memory")
#define CP_WAIT0()  asm volatile("cp.async.wait_group 0;" ::: "memory")

#define ABLK 528
#define AREG (16 * ABLK)
#define BBUF 81920

#define A_OFF    0
#define B_OFF    (4 * AREG)
#define RED_OFF  (B_OFF + 2 * BBUF)
#define SRC_OFF  (RED_OFF + 6144)
#define DST_OFF  (SRC_OFF + 256)
#define GE_OFF   (DST_OFF + 256)
#define SM_TOTAL (GE_OFF + 256)

template <int NACT>
__device__ __forceinline__ void mma_chunk(
    float acc[2][NB_PER_W][4],
    const char* ah, const char* al, const char* bB,
    int mw, int lane, const int* slist, const int* alist)
{
    #pragma unroll
    for (int ks = 0; ks < 4; ks++) {
        uint32_t afh[2][4], afl[2][4];
        #pragma unroll
        for (int f = 0; f < 2; f++) {
            uint32_t boff = (uint32_t)((mw * 2 + f) * 4 + ks) * ABLK + lane * 16;
            uint4 vh = *(const uint4*)(ah + boff);
            uint4 vl = *(const uint4*)(al + boff);
            afh[f][0] = vh.x; afh[f][1] = vh.y; afh[f][2] = vh.z; afh[f][3] = vh.w;
            afl[f][0] = vl.x; afl[f][1] = vl.y; afl[f][2] = vl.z; afl[f][3] = vl.w;
        }
        #pragma unroll
        for (int i = 0; i < NACT; i++) {
            const int sl = slist[i];
            uint4 v = *(const uint4*)(bB + (((uint32_t)alist[i] * 4 + ks) * 32 + lane) * 16);
            #pragma unroll
            for (int f = 0; f < 2; f++) {
                mma16816(acc[f][sl], afh[f], v.x, v.y);
                mma16816(acc[f][sl], afh[f], v.z, v.w);
                mma16816(acc[f][sl], afl[f], v.x, v.y);
            }
        }
    }
}

// FULL tile body (valid edges: all paths + softmax combine).
// __forceinline__ is load-bearing: ABI call spills (round-13 regression).
__device__ __forceinline__ void tile_body_full(
    int ebase, int nv,
    char* smem, uint32_t smem_u32,
    const float* __restrict__ z, const float* __restrict__ chem,
    const int*   __restrict__ edge,
    const float* __restrict__ sb2, const float* __restrict__ cb2,
    const float* __restrict__ mb2, const float* __restrict__ pw,
    float* __restrict__ out)
{
    const int tid  = threadIdx.x;
    const int wid  = tid >> 5;
    const int lane = tid & 31;
    const int nw   = wid & 7;
    const int mw   = wid >> 3;

    int*   Ssrc = (int*)(smem + SRC_OFF);
    int*   Sdst = (int*)(smem + DST_OFF);
    int*   Sge  = (int*)(smem + GE_OFF);
    float* red  = (float*)(smem + RED_OFF);

    if (tid < TILE_E) {
        int li = ebase + tid;
        int ge = g_valid[(li < nv) ? li : (nv - 1)];
        Sge[tid] = (li < nv) ? ge : -1;
        Ssrc[tid] = edge[2 * ge + 0];
        Sdst[tid] = edge[2 * ge + 1];
    }
    for (int i = tid; i < NWARP_N * 3 * TILE_E; i += THREADS)
        red[i] = 0.f;
    __syncthreads();

    const int ge_ = tid >> 3;
    const int q   = tid & 7;
    const int r   = ge_ & 15;
    const int fm  = ge_ >> 4;
    const uint32_t abase = (uint32_t)(fm * 4 + (q >> 1)) * ABLK
                         + (uint32_t)((r & 7) * 64 + (r >> 3) * 4 + (q & 1) * 8);
    const int srow = Ssrc[ge_];
    const int drow = Sdst[ge_];

    const int sl_z[3] = { 0, 4, 5 };
    const int ab_z[3] = { nw, 8 + 2 * nw, 9 + 2 * nw };
    const int sl_c[5] = { 1, 2, 3, 4, 5 };
    const int ab_c[5] = { 3 * nw, 3 * nw + 1, 3 * nw + 2, 24 + 2 * nw, 25 + 2 * nw };

    float4 ga[2], gb[2];
    {
        const float* sp = z + (size_t)srow * 128 + q * 8;
        const float* dp = z + (size_t)drow * 128 + q * 8;
        ga[0] = *(const float4*)(sp);     ga[1] = *(const float4*)(sp + 4);
        gb[0] = *(const float4*)(dp);     gb[1] = *(const float4*)(dp + 4);
    }
    {
        for (uint32_t i = tid; i < 49152 / 16; i += THREADS)
            cp_async16(smem_u32 + B_OFF + i * 16, g_Bpk + i * 16);
        CP_COMMIT();
    }

    float acc[2][NB_PER_W][4];
    #pragma unroll
    for (int a = 0; a < 2; a++)
        #pragma unroll
        for (int b = 0; b < NB_PER_W; b++)
            #pragma unroll
            for (int qq = 0; qq < 4; qq++) acc[a][b][qq] = 0.f;

    #pragma unroll 1
    for (int c = 0; c < NCH; c++) {
        {
            char* sah = smem + A_OFF + ((c & 1) * 2 + 0) * AREG;
            char* sal = smem + A_OFF + ((c & 1) * 2 + 1) * AREG;
            #pragma unroll
            for (int i = 0; i < 2; i++) {
                float p0 = ga[i].x * gb[i].x;
                float p1 = ga[i].y * gb[i].y;
                float p2 = ga[i].z * gb[i].z;
                float p3 = ga[i].w * gb[i].w;
                __nv_bfloat16 h0 = __float2bfloat16(p0), h1 = __float2bfloat16(p1);
                __nv_bfloat16 h2 = __float2bfloat16(p2), h3 = __float2bfloat16(p3);
                float l0 = p0 - __bfloat162float(h0);
                float l1 = p1 - __bfloat162float(h1);
                float l2 = p2 - __bfloat162float(h2);
                float l3 = p3 - __bfloat162float(h3);
                uint32_t hi01 = ((uint32_t)__bfloat16_as_ushort(h0)) | ((uint32_t)__bfloat16_as_ushort(h1) << 16);
                uint32_t hi23 = ((uint32_t)__bfloat16_as_ushort(h2)) | ((uint32_t)__bfloat16_as_ushort(h3) << 16);
                uint32_t lo01 = pack_bf16x2(l0, l1);
                uint32_t lo23 = pack_bf16x2(l2, l3);
                uint32_t a0 = abase + (uint32_t)(i * 32);
                uint32_t a1 = a0 + 16;
                *(uint32_t*)(sah + a0) = hi01;
                *(uint32_t*)(sah + a1) = hi23;
                *(uint32_t*)(sal + a0) = lo01;
                *(uint32_t*)(sal + a1) = lo23;
            }
        }
        CP_WAIT0();
        __syncthreads();

        if (c + 1 < NCH) {
            int cn = c + 1;
            uint32_t nb16  = ((cn < 2) ? 49152u : 81920u) >> 4;
            uint32_t cbase = (cn < 2) ? (uint32_t)cn * 49152u
                                      : 98304u + (uint32_t)(cn - 2) * 81920u;
            uint32_t bdst = smem_u32 + B_OFF + (uint32_t)(cn & 1) * BBUF;
            const unsigned char* gsrc = g_Bpk + cbase;
            for (uint32_t i = tid; i < nb16; i += THREADS)
                cp_async16(bdst + i * 16, gsrc + i * 16);
            CP_COMMIT();
        }

        if (c + 1 < NCH) {
            int cn = c + 1;
            const float* basep = (cn < 2) ? z : chem;
            int ldr = (cn < 2) ? 128 : 768;
            int kb  = (cn < 2) ? cn * 64 : (cn - 2) * 64;
            const float* sp = basep + (size_t)srow * ldr + kb + q * 8;
            const float* dp = basep + (size_t)drow * ldr + kb + q * 8;
            ga[0] = *(const float4*)(sp);     ga[1] = *(const float4*)(sp + 4);
            gb[0] = *(const float4*)(dp);     gb[1] = *(const float4*)(dp + 4);
        }

        {
            const char* ah = smem + A_OFF + ((c & 1) * 2 + 0) * AREG;
            const char* al = smem + A_OFF + ((c & 1) * 2 + 1) * AREG;
            const char* bB = smem + B_OFF + (c & 1) * BBUF;
            if (c < 2) mma_chunk<3>(acc, ah, al, bB, mw, lane, sl_z, ab_z);
            else       mma_chunk<5>(acc, ah, al, bB, mw, lane, sl_c, ab_c);
        }
    }
    __syncthreads();

    {
        const int nbg[NB_PER_W] = { nw, 8 + nw * 3, 9 + nw * 3, 10 + nw * 3,
                                    32 + nw * 2, 33 + nw * 2 };
        const int qc = (lane & 3) * 2;
        float ps[4][3];
        #pragma unroll
        for (int s = 0; s < 4; s++)
            #pragma unroll
            for (int p = 0; p < 3; p++) ps[s][p] = 0.f;

        #pragma unroll
        for (int sl = 0; sl < NB_PER_W; sl++) {
            int col0 = nbg[sl] * 8;
            int p = (sl == 0) ? 0 : (sl < 4) ? 1 : 2;
            float bb0 = g_b1[col0 + qc],     bb1 = g_b1[col0 + qc + 1];
            float ww0 = g_w2[col0 + qc],     ww1 = g_w2[col0 + qc + 1];
            #pragma unroll
            for (int f = 0; f < 2; f++) {
                const float* a = acc[f][sl];
                ps[f * 2 + 0][p] += fmaxf(a[0] + bb0, 0.f) * ww0 + fmaxf(a[1] + bb1, 0.f) * ww1;
                ps[f * 2 + 1][p] += fmaxf(a[2] + bb0, 0.f) * ww0 + fmaxf(a[3] + bb1, 0.f) * ww1;
            }
        }
        #pragma unroll
        for (int s = 0; s < 4; s++)
            #pragma unroll
            for (int p = 0; p < 3; p++) {
                float v = ps[s][p];
                v += __shfl_xor_sync(0xffffffffu, v, 1);
                v += __shfl_xor_sync(0xffffffffu, v, 2);
                ps[s][p] = v;
            }
        if ((lane & 3) == 0) {
            #pragma unroll
            for (int f = 0; f < 2; f++)
                #pragma unroll
                for (int rr = 0; rr < 2; rr++) {
                    int el = (mw * 2 + f) * 16 + (lane >> 2) + rr * 8;
                    #pragma unroll
                    for (int p = 0; p < 3; p++)
                        red[(nw * 3 + p) * TILE_E + el] += ps[f * 2 + rr][p];
                }
        }
    }
    __syncthreads();

    if (tid < TILE_E && Sge[tid] >= 0) {
        float s0 = 0.f, s1 = 0.f, s2 = 0.f;
        #pragma unroll
        for (int w = 0; w < NWARP_N; w++) {
            s0 += red[(w * 3 + 0) * TILE_E + tid];
            s1 += red[(w * 3 + 1) * TILE_E + tid];
            s2 += red[(w * 3 + 2) * TILE_E + tid];
        }
        float p0 = pw[0], p1 = pw[1], p2 = pw[2];
        float mx = fmaxf(p0, fmaxf(p1, p2));
        float e0 = expf(p0 - mx), e1 = expf(p1 - mx), e2 = expf(p2 - mx);
        float inv = 1.f / (e0 + e1 + e2);
        float ss = s0 + sb2[0];
        float sc = s1 + cb2[0];
        float sm = s2 + mb2[0];
        out[Sge[tid]] = (e0 * ss + e1 * sc + e2 * sm) * inv;
    }
}

__global__ void __launch_bounds__(THREADS, 1)
decoder_full(
    const float* __restrict__ z, const float* __restrict__ chem,
    const int*   __restrict__ edge,
    const float* __restrict__ sb2, const float* __restrict__ cb2,
    const float* __restrict__ mb2, const float* __restrict__ pw,
    float* __restrict__ out)
{
    const int nv = g_cnt[0];
    const int ebase = blockIdx.x * TILE_E;
    if (ebase >= nv) return;
    extern __shared__ __align__(16) char smem[];
    uint32_t smem_u32;
    asm("{ .reg .u64 t; cvta.to.shared.u64 t, %1; cvt.u32.u64 %0, t; }"
        : "=r"(smem_u32) : "l"(smem));
    tile_body_full(ebase, nv, smem, smem_u32,
                   z, chem, edge, sb2, cb2, mb2, pw, out);
}

// ============================================================================
// Lean STRUCT kernel: 64 invalid edges/CTA, structural path only.
// B (32 KB) loaded once; single A stage over all 128 k; 2 CTAs/SM.
// ============================================================================
#define T_S        512
#define TILE_S     64
#define SAREG_S    (32 * ABLK)                 // 4 fm x 8 ks blocks = 16896 per split
#define SA_OFF_S   0
#define SB_OFF_S   (2 * SAREG_S)               // 33792
#define SRED_OFF_S (SB_OFF_S + 32768)          // 8 x 64 floats = 2048
#define SGE_OFF_S  (SRED_OFF_S + 2048)
#define SSRC_OFF_S (SGE_OFF_S + 256)
#define SDST_OFF_S (SSRC_OFF_S + 256)
#define SM_S_TOTAL (SDST_OFF_S + 256)

__global__ void __launch_bounds__(T_S, 2)
decoder_struct(
    const float* __restrict__ z, const int* __restrict__ edge,
    const float* __restrict__ sb2, float* __restrict__ out)
{
    const int ni = g_cnt[1];
    const int ebase = blockIdx.x * TILE_S;
    if (ebase >= ni) return;

    extern __shared__ __align__(16) char smem[];
    uint32_t smem_u32;
    asm("{ .reg .u64 t; cvta.to.shared.u64 t, %1; cvt.u32.u64 %0, t; }"
        : "=r"(smem_u32) : "l"(smem));

    const int tid  = threadIdx.x;
    const int wid  = tid >> 5;
    const int lane = tid & 31;
    const int nw   = wid & 7;
    const int mw   = wid >> 3;

    int*   Ssrc = (int*)(smem + SSRC_OFF_S);
    int*   Sdst = (int*)(smem + SDST_OFF_S);
    int*   Sge  = (int*)(smem + SGE_OFF_S);
    float* red  = (float*)(smem + SRED_OFF_S);

    if (tid < TILE_S) {
        int li = ebase + tid;
        int ge = g_invalid[(li < ni) ? li : (ni - 1)];
        Sge[tid] = (li < ni) ? ge : -1;
        Ssrc[tid] = edge[2 * ge + 0];
        Sdst[tid] = edge[2 * ge + 1];
    }
    // B once: chunk0 structural (first 16KB of g_Bpk) + chunk1 structural
    for (int i = tid; i < 2048; i += T_S) {
        const unsigned char* src = (i < 1024) ? (g_Bpk + i * 16)
                                              : (g_Bpk + 49152 + (i - 1024) * 16);
        cp_async16(smem_u32 + SB_OFF_S + (uint32_t)i * 16, src);
    }
    CP_COMMIT();
    __syncthreads();

    // gather + stage full 128-k row: e = tid/8, q = tid%8 = ks (16 k each)
    {
        const int e  = tid >> 3;
        const int q  = tid & 7;
        const int r  = e & 15;
        const int fm = e >> 4;
        const uint32_t base = (uint32_t)(fm * 8 + q) * ABLK
                            + (uint32_t)((r & 7) * 64 + (r >> 3) * 4);
        const float* sp = z + (size_t)Ssrc[e] * 128 + q * 16;
        const float* dp = z + (size_t)Sdst[e] * 128 + q * 16;
        char* sah = smem + SA_OFF_S;
        char* sal = smem + SA_OFF_S + SAREG_S;
        #pragma unroll
        for (int g = 0; g < 4; g++) {
            float4 a4 = *(const float4*)(sp + g * 4);
            float4 b4 = *(const float4*)(dp + g * 4);
            float p0 = a4.x * b4.x, p1 = a4.y * b4.y;
            float p2 = a4.z * b4.z, p3 = a4.w * b4.w;
            __nv_bfloat16 h0 = __float2bfloat16(p0), h1 = __float2bfloat16(p1);
            __nv_bfloat16 h2 = __float2bfloat16(p2), h3 = __float2bfloat16(p3);
            float l0 = p0 - __bfloat162float(h0);
            float l1 = p1 - __bfloat162float(h1);
            float l2 = p2 - __bfloat162float(h2);
            float l3 = p3 - __bfloat162float(h3);
            uint32_t hi01 = ((uint32_t)__bfloat16_as_ushort(h0)) | ((uint32_t)__bfloat16_as_ushort(h1) << 16);
            uint32_t hi23 = ((uint32_t)__bfloat16_as_ushort(h2)) | ((uint32_t)__bfloat16_as_ushort(h3) << 16);
            uint32_t lo01 = pack_bf16x2(l0, l1);
            uint32_t lo23 = pack_bf16x2(l2, l3);
            uint32_t a0 = base + (uint32_t)((g >> 1) * 8 + (g & 1) * 32);
            uint32_t a1 = a0 + 16;
            *(uint32_t*)(sah + a0) = hi01;
            *(uint32_t*)(sah + a1) = hi23;
            *(uint32_t*)(sal + a0) = lo01;
            *(uint32_t*)(sal + a1) = lo23;
        }
    }
    CP_WAIT0();
    __syncthreads();

    // MMA: 8 ks-steps, 1 structural block per warp
    float acc[2][4];
    #pragma unroll
    for (int f = 0; f < 2; f++)
        #pragma unroll
        for (int qq = 0; qq < 4; qq++) acc[f][qq] = 0.f;

    const char* sah = smem + SA_OFF_S;
    const char* sal = smem + SA_OFF_S + SAREG_S;
    const char* bB  = smem + SB_OFF_S;
    #pragma unroll
    for (int ks = 0; ks < 8; ks++) {
        const int c   = ks >> 2;
        const int ksl = ks & 3;
        uint4 v = *(const uint4*)(bB + (uint32_t)(c * 16384 + nw * 2048)
                                     + (uint32_t)(ksl * 32 + lane) * 16);
        #pragma unroll
        for (int f = 0; f < 2; f++) {
            uint32_t boff = (uint32_t)((mw * 2 + f) * 8 + ks) * ABLK + lane * 16;
            uint4 vh = *(const uint4*)(sah + boff);
            uint4 vl = *(const uint4*)(sal + boff);
            uint32_t afh[4] = { vh.x, vh.y, vh.z, vh.w };
            uint32_t afl[4] = { vl.x, vl.y, vl.z, vl.w };
            mma16816(acc[f], afh, v.x, v.y);
            mma16816(acc[f], afh, v.z, v.w);
            mma16816(acc[f], afl, v.x, v.y);
        }
    }

    // epilogue: bias + ReLU + w2, quad reduce, per-warp slot in red
    {
        const int qc = (lane & 3) * 2;
        const int col0 = nw * 8;
        float bb0 = g_b1[col0 + qc],     bb1 = g_b1[col0 + qc + 1];
        float ww0 = g_w2[col0 + qc],     ww1 = g_w2[col0 + qc + 1];
        float ps[4];
        #pragma unroll
        for (int f = 0; f < 2; f++) {
            ps[f * 2 + 0] = fmaxf(acc[f][0] + bb0, 0.f) * ww0 + fmaxf(acc[f][1] + bb1, 0.f) * ww1;
            ps[f * 2 + 1] = fmaxf(acc[f][2] + bb0, 0.f) * ww0 + fmaxf(acc[f][3] + bb1, 0.f) * ww1;
        }
        #pragma unroll
        for (int s = 0; s < 4; s++) {
            float v = ps[s];
            v += __shfl_xor_sync(0xffffffffu, v, 1);
            v += __shfl_xor_sync(0xffffffffu, v, 2);
            ps[s] = v;
        }
        if ((lane & 3) == 0) {
            #pragma unroll
            for (int f = 0; f < 2; f++)
                #pragma unroll
                for (int rr = 0; rr < 2; rr++) {
                    int el = (mw * 2 + f) * 16 + (lane >> 2) + rr * 8;
                    red[nw * TILE_S + el] = ps[f * 2 + rr];
                }
        }
    }
    __syncthreads();

    if (tid < TILE_S && Sge[tid] >= 0) {
        float s0 = 0.f;
        #pragma unroll
        for (int w = 0; w < NWARP_N; w++)
            s0 += red[w * TILE_S + tid];
        out[Sge[tid]] = s0 + sb2[0];
    }
}

extern "C" void kernel_launch(void* const* d_in, const int* in_sizes, int n_in,
                              void* d_out, int out_size)
{
    const float* z    = (const float*)d_in[0];
    const float* chem = (const float*)d_in[1];
    const int*   edge = (const int*)d_in[2];
    const int*   mask = (const int*)d_in[3];
    const float* sw1  = (const float*)d_in[4];
    const float* sb1  = (const float*)d_in[5];
    const float* sw2  = (const float*)d_in[6];
    const float* sb2  = (const float*)d_in[7];
    const float* cw1  = (const float*)d_in[8];
    const float* cb1  = (const float*)d_in[9];
    const float* cw2  = (const float*)d_in[10];
    const float* cb2  = (const float*)d_in[11];
    const float* mw1  = (const float*)d_in[12];
    const float* mb1  = (const float*)d_in[13];
    const float* mw2  = (const float*)d_in[14];
    const float* mb2  = (const float*)d_in[15];
    const float* pw   = (const float*)d_in[16];
    float*       out  = (float*)d_out;

    const int E = in_sizes[2] / 2;

    zero_kernel<<<1, 1>>>();
    compact_kernel<<<(E + 511) / 512, 512>>>(edge, mask, E);
    {
        int total = KTOT * HTOT + HTOT;
        pack_kernel<<<(total + 255) / 256, 256>>>(sw1, sb1, sw2,
                                                  cw1, cb1, cw2,
                                                  mw1, mb1, mw2);
    }

    cudaFuncSetAttribute(decoder_full,
                         cudaFuncAttributeMaxDynamicSharedMemorySize, SM_TOTAL);
    cudaFuncSetAttribute(decoder_struct,
                         cudaFuncAttributeMaxDynamicSharedMemorySize, SM_S_TOTAL);

    const int ntiles = (E + TILE_E - 1) / TILE_E;
    decoder_full<<<ntiles, THREADS, SM_TOTAL>>>(
        z, chem, edge, sb2, cb2, mb2, pw, out);
    const int nst = (E + TILE_S - 1) / TILE_S;
    decoder_struct<<<nst, T_S, SM_S_TOTAL>>>(z, edge, sb2, out);
}